// round 8
// baseline (speedup 1.0000x reference)
#include <cuda_runtime.h>
#include <cstdint>
#include <math.h>

typedef unsigned int uint;

#define C_DIM 512
#define NE    256
#define HW    4096
#define NBLK  512
#define NSTG  32
#define THR   1e-3f

__device__ __align__(16) float g_whiP[NE * C_DIM];  // fragment-permuted tf32 hi
__device__ __align__(16) float g_wloP[NE * C_DIM];  // fragment-permuted tf32 lo
__device__ __align__(16) float g_wT [C_DIM * NE];   // fp32 codebook [c][j]
__device__ __align__(16) float g_pw [C_DIM * NE];   // projected codebook [o][j]
__device__ float g_n[NE];
__device__ int   g_hist[NE];
__device__ float g_partial[NBLK];

// stage layout: AHI[2][256][48B] | ALO | BHI[2][128][40B] | BLO
#define APL   12288
#define AHALF 24576
#define OFF_B 49152
#define BPL   5120
#define BHALF 10240
#define STAGE 69632
#define OFF_AP   139264
#define OFF_AT   140288
#define OFF_NRM  140800
#define OFF_IDX  141824
#define OFF_CD   142336
#define OFF_CI   144384
#define OFF_C2   146432
#define OFF_D1   148480
#define OFF_DS   148992
#define OFF_FC   149008
#define OFF_RD   149024
#define OFF_RI   149152
#define OFF_FL   149280
#define OFF_ZC   149792
#define OFF_HIST 151840
#define SMEM_TOTAL 152864

__device__ __forceinline__ uint s2u(const void* p) {
    uint a;
    asm("{ .reg .u64 t; cvta.to.shared.u64 t, %1; cvt.u32.u64 %0, t; }" : "=r"(a) : "l"(p));
    return a;
}
__device__ __forceinline__ float tf32r(float x) {
    uint r; asm("cvt.rna.tf32.f32 %0, %1;" : "=r"(r) : "f"(x));
    return __uint_as_float(r);
}
__device__ __forceinline__ void mma8(float* c, uint a0, uint a1, uint a2, uint a3,
                                     uint b0, uint b1) {
    asm volatile("mma.sync.aligned.m16n8k8.row.col.f32.tf32.tf32.f32 "
                 "{%0,%1,%2,%3}, {%4,%5,%6,%7}, {%8,%9}, {%0,%1,%2,%3};"
                 : "+f"(c[0]), "+f"(c[1]), "+f"(c[2]), "+f"(c[3])
                 : "r"(a0), "r"(a1), "r"(a2), "r"(a3), "r"(b0), "r"(b1));
}
#define CP16(dst, src) \
    asm volatile("cp.async.cg.shared.global [%0], [%1], 16;" :: "r"(dst), "l"(src))
#define CPCOMMIT() asm volatile("cp.async.commit_group;")
#define CPWAIT0()  asm volatile("cp.async.wait_group 0;")

__global__ void k_init() { g_hist[threadIdx.x] = 0; }

// grid 256 (code j), block 512 (channel c)
__global__ void k_prep_w(const float* __restrict__ emb,
                         const float* __restrict__ stdp,
                         const float* __restrict__ means) {
    __shared__ float wsum[16];
    int j = blockIdx.x, c = threadIdx.x;
    float s = fabsf(stdp[0]);
    float m = __fdiv_rn(means[0] + means[1] + means[2], 3.0f);
    float e = emb[(size_t)j * C_DIM + c];
    float v = __fadd_rn(__fmul_rn(e, s), m);
    g_wT[c * NE + j] = v;
    float hi = tf32r(v), lo = tf32r(v - hi);
    int chunk = c >> 4, p = (c >> 3) & 1, kin = c & 7;
    int pos = (kin & 3) * 2 + (kin >> 2);
    int flat = chunk * 4096 + p * 2048 + j * 8 + pos;
    g_whiP[flat] = hi;
    g_wloP[flat] = lo;
    float sq = v * v;
#pragma unroll
    for (int o = 16; o > 0; o >>= 1) sq += __shfl_xor_sync(0xffffffffu, sq, o);
    if ((c & 31) == 0) wsum[c >> 5] = sq;
    __syncthreads();
    if (c == 0) {
        float a = 0.f;
#pragma unroll
        for (int i = 0; i < 16; i++) a += wsum[i];
        g_n[j] = a;
    }
}

// grid 256 (2 channels each), block 256 (code j)
__global__ void k_prep_pw(const float* __restrict__ convw,
                          const float* __restrict__ convb) {
    __shared__ float cw[2][512];
    int bo = blockIdx.x * 2, j = threadIdx.x;
#pragma unroll
    for (int p = 0; p < 4; p++) {
        int i = j + 256 * p;
        cw[i >> 9][i & 511] = convw[(size_t)bo * 512 + i];
    }
    __syncthreads();
    float a0 = 0.f, a1 = 0.f;
#pragma unroll 8
    for (int c = 0; c < C_DIM; c++) {
        float wv = g_wT[c * NE + j];
        a0 = fmaf(cw[0][c], wv, a0);
        a1 = fmaf(cw[1][c], wv, a1);
    }
    g_pw[(size_t)bo * NE + j]       = __fadd_rn(a0, convb[bo]);
    g_pw[(size_t)(bo + 1) * NE + j] = __fadd_rn(a1, convb[bo + 1]);
}

__global__ __launch_bounds__(256, 1) void k_main(const float* __restrict__ z,
                                                 float* __restrict__ out) {
    extern __shared__ __align__(1024) char sm[];
    const uint sb = s2u(sm);
    const int tid = threadIdx.x;
    const int lane = tid & 31, warp = tid >> 5;
    const int g = lane >> 2, tig = lane & 3;
    const int wm = warp >> 1, wn = warp & 1;
    const int tok = tid & 127, h = tid >> 7;
    const int b = blockIdx.x >> 5;
    const int hw0 = (blockIdx.x & 31) << 7;
    const float* zb = z + (size_t)b * C_DIM * HW + hw0;

    ((int*)(sm + OFF_HIST))[tid] = 0;
    ((float*)(sm + OFF_NRM))[tid] = g_n[tid];
    if (tid == 0) *(int*)(sm + OFF_FC) = 0;

    float acc[4][8][4];
#pragma unroll
    for (int mt = 0; mt < 4; mt++)
#pragma unroll
        for (int nt = 0; nt < 8; nt++)
#pragma unroll
            for (int q = 0; q < 4; q++) acc[mt][nt][q] = 0.f;
    float regA = 0.f;
    float zr[8];

#define LDZ(s) do { \
    _Pragma("unroll") \
    for (int i = 0; i < 8; i++) zr[i] = zb[(size_t)((s) * 16 + h * 8 + i) * HW + tok]; \
    _Pragma("unroll") \
    for (int i = 0; i < 8; i++) regA = fmaf(zr[i], zr[i], regA); } while (0)

#define STZ(buf) do { \
    char* B_ = sm + (buf) * STAGE + OFF_B + h * BPL + tok * 40; \
    _Pragma("unroll") \
    for (int p = 0; p < 4; p++) { \
        float hx = tf32r(zr[p]), hy = tf32r(zr[p + 4]); \
        *(float2*)(B_ + p * 8) = make_float2(hx, hy); \
        *(float2*)(B_ + BHALF + p * 8) = make_float2(tf32r(zr[p] - hx), tf32r(zr[p + 4] - hy)); \
    } } while (0)

#define CB(s, buf) do { \
    _Pragma("unroll") \
    for (int i = 0; i < 4; i++) { \
        int q = tid + 256 * i; \
        int p_ = q >> 9, m_ = (q >> 1) & 255, hf = q & 1; \
        uint dst = sb + (buf) * STAGE + p_ * APL + m_ * 48 + hf * 16; \
        CP16(dst, (const char*)g_whiP + (size_t)(s) * 16384 + q * 16); \
        CP16(dst + AHALF, (const char*)g_wloP + (size_t)(s) * 16384 + q * 16); \
    } \
    CPCOMMIT(); } while (0)

#define COMPUTE(buf) do { \
    _Pragma("unroll") \
    for (int p = 0; p < 2; p++) { \
        const char* Ah = sm + (buf) * STAGE + p * APL + (wm * 64 + g) * 48 + tig * 8; \
        const char* Bh = sm + (buf) * STAGE + OFF_B + p * BPL + (wn * 64 + g) * 40 + tig * 8; \
        uint2 BHf[8], BLf[8]; \
        _Pragma("unroll") \
        for (int nt = 0; nt < 8; nt++) { \
            BHf[nt] = *(const uint2*)(Bh + nt * 320); \
            BLf[nt] = *(const uint2*)(Bh + BHALF + nt * 320); \
        } \
        _Pragma("unroll") \
        for (int mt = 0; mt < 4; mt++) { \
            uint2 h0 = *(const uint2*)(Ah + mt * 768); \
            uint2 h1 = *(const uint2*)(Ah + mt * 768 + 384); \
            uint2 l0 = *(const uint2*)(Ah + AHALF + mt * 768); \
            uint2 l1 = *(const uint2*)(Ah + AHALF + mt * 768 + 384); \
            _Pragma("unroll") \
            for (int nt = 0; nt < 8; nt++) { \
                mma8(acc[mt][nt], h0.x, h1.x, h0.y, h1.y, BHf[nt].x, BHf[nt].y); \
                mma8(acc[mt][nt], h0.x, h1.x, h0.y, h1.y, BLf[nt].x, BLf[nt].y); \
                mma8(acc[mt][nt], l0.x, l1.x, l0.y, l1.y, BHf[nt].x, BHf[nt].y); \
            } \
        } \
    } } while (0)

    // prologue
    CB(0, 0);
    LDZ(0); STZ(0);
    LDZ(1);
    CPWAIT0();
    __syncthreads();

    for (int s = 0; s < NSTG; s++) {
        const int buf = s & 1;
        if (s < NSTG - 1) {
            STZ(buf ^ 1);
            CB(s + 1, buf ^ 1);
            if (s < NSTG - 2) LDZ(s + 2);
        }
        COMPUTE(buf);
        if (s < NSTG - 1) CPWAIT0();
        __syncthreads();
    }

    // ---- epilogue: per-token argmin with second-best tracking ----
    ((float*)(sm + OFF_AP))[h * 128 + tok] = regA;
    __syncthreads();
    if (tid < 128)
        ((float*)(sm + OFF_AT))[tid] =
            ((float*)(sm + OFF_AP))[tid] + ((float*)(sm + OFF_AP))[128 + tid];
    __syncthreads();

    const float* s_n = (const float*)(sm + OFF_NRM);
    const float* s_at = (const float*)(sm + OFF_AT);
#pragma unroll
    for (int nt = 0; nt < 8; nt++)
#pragma unroll
        for (int par = 0; par < 2; par++) {
            int t = wn * 64 + nt * 8 + 2 * tig + par;
            float At = s_at[t];
            float bd = __int_as_float(0x7f800000);
            float bd2 = bd;
            int bi = 0;
#pragma unroll
            for (int mt = 0; mt < 4; mt++) {
                int j0 = wm * 64 + mt * 16 + g;
                float d0 = __fadd_rn(__fadd_rn(At, s_n[j0]), -2.0f * acc[mt][nt][par]);
                float d1 = __fadd_rn(__fadd_rn(At, s_n[j0 + 8]), -2.0f * acc[mt][nt][2 + par]);
                if (d0 < bd) { bd2 = bd; bd = d0; bi = j0; } else if (d0 < bd2) bd2 = d0;
                if (d1 < bd) { bd2 = bd; bd = d1; bi = j0 + 8; } else if (d1 < bd2) bd2 = d1;
            }
#pragma unroll
            for (int o = 16; o >= 4; o >>= 1) {
                float od  = __shfl_xor_sync(0xffffffffu, bd, o);
                int   oi  = __shfl_xor_sync(0xffffffffu, bi, o);
                float od2 = __shfl_xor_sync(0xffffffffu, bd2, o);
                float nd2 = fminf(fmaxf(bd, od), fminf(bd2, od2));
                if (od < bd || (od == bd && oi < bi)) { bd = od; bi = oi; }
                bd2 = nd2;
            }
            if (g == 0) {
                ((float*)(sm + OFF_CD))[wm * 128 + t] = bd;
                ((int*)(sm + OFF_CI))[wm * 128 + t] = bi;
                ((float*)(sm + OFF_C2))[wm * 128 + t] = bd2;
            }
        }
    __syncthreads();

    float* P0 = (float*)sm;
    float* P1 = (float*)(sm + 32768);
    if (tid < 128) {
        float bd = ((float*)(sm + OFF_CD))[tid];
        int bi = ((int*)(sm + OFF_CI))[tid];
        float bd2 = ((float*)(sm + OFF_C2))[tid];
#pragma unroll
        for (int w = 1; w < 4; w++) {
            float d  = ((float*)(sm + OFF_CD))[w * 128 + tid];
            int   i2 = ((int*)(sm + OFF_CI))[w * 128 + tid];
            float e2 = ((float*)(sm + OFF_C2))[w * 128 + tid];
            float nd2 = fminf(fmaxf(bd, d), fminf(bd2, e2));
            if (d < bd || (d == bd && i2 < bi)) { bd = d; bi = i2; }
            bd2 = nd2;
        }
        ((int*)(sm + OFF_IDX))[tid] = bi;
        ((float*)(sm + OFF_D1))[tid] = bd;
        if (bd2 - bd < THR) {
            int p = atomicAdd((int*)(sm + OFF_FC), 1);
            ((int*)(sm + OFF_FL))[p] = tid;
        }
    } else {
        int id = tid - 128;
#pragma unroll
        for (int p = 0; p < 16; p++)
            ((float4*)P0)[id + 128 * p] = ((const float4*)g_pw)[id + 128 * p];
    }
    __syncthreads();

    // ---- exact fp32 recheck for near-tie tokens ----
    const int cnt = *(const int*)(sm + OFF_FC);
    float* zcol = (float*)(sm + OFF_ZC);
    for (int q = 0; q < cnt; q++) {
        const int tk = ((const int*)(sm + OFF_FL))[q];
        zcol[tid]       = zb[(size_t)tid * HW + tk];
        zcol[tid + 256] = zb[(size_t)(tid + 256) * HW + tk];
        __syncthreads();
        float dot = 0.f;
#pragma unroll 8
        for (int c = 0; c < C_DIM; c++)
            dot = fmaf(zcol[c], g_wT[c * NE + tid], dot);
        float bd = __fadd_rn(__fadd_rn(s_at[tk], s_n[tid]), -2.0f * dot);
        int bi = tid;
#pragma unroll
        for (int o = 16; o > 0; o >>= 1) {
            float od = __shfl_xor_sync(0xffffffffu, bd, o);
            int   oi = __shfl_xor_sync(0xffffffffu, bi, o);
            if (od < bd || (od == bd && oi < bi)) { bd = od; bi = oi; }
        }
        if (lane == 0) {
            ((float*)(sm + OFF_RD))[warp] = bd;
            ((int*)(sm + OFF_RI))[warp] = bi;
        }
        __syncthreads();
        if (tid == 0) {
            float fb = ((float*)(sm + OFF_RD))[0];
            int fi = ((int*)(sm + OFF_RI))[0];
#pragma unroll
            for (int w = 1; w < 8; w++) {
                float d = ((float*)(sm + OFF_RD))[w];
                int i2 = ((int*)(sm + OFF_RI))[w];
                if (d < fb || (d == fb && i2 < fi)) { fb = d; fi = i2; }
            }
            ((int*)(sm + OFF_IDX))[tk] = fi;
            ((float*)(sm + OFF_D1))[tk] = fb;
        }
        __syncthreads();
    }

    // ---- histogram + loss from corrected results ----
    if (tid < 128) {
        atomicAdd(&((int*)(sm + OFF_HIST))[((const int*)(sm + OFF_IDX))[tid]], 1);
        float v = ((const float*)(sm + OFF_D1))[tid];
#pragma unroll
        for (int o = 16; o > 0; o >>= 1) v += __shfl_xor_sync(0xffffffffu, v, o);
        if (lane == 0) ((float*)(sm + OFF_DS))[warp] = v;
    }
    __syncthreads();
    if (tid == 0) {
        float* ds = (float*)(sm + OFF_DS);
        g_partial[blockIdx.x] = ds[0] + ds[1] + ds[2] + ds[3];
    }
    atomicAdd(&g_hist[tid], ((int*)(sm + OFF_HIST))[tid]);

    // ---- output gather ----
    const int mi = (tid < 128) ? ((const int*)(sm + OFF_IDX))[tid] : 0;
    const size_t outbase = (size_t)b * C_DIM * HW + hw0;
    for (int ch = 0; ch < 16; ch++) {
        float* cur = (ch & 1) ? P1 : P0;
        float* nxt = (ch & 1) ? P0 : P1;
        if (tid < 128) {
#pragma unroll 8
            for (int r = 0; r < 32; r++)
                out[outbase + (size_t)(ch * 32 + r) * HW + tid] = cur[r * NE + mi];
        } else if (ch < 15) {
            int id = tid - 128;
#pragma unroll
            for (int p = 0; p < 16; p++)
                ((float4*)nxt)[id + 128 * p] =
                    ((const float4*)g_pw)[(ch + 1) * 2048 + id + 128 * p];
        }
        __syncthreads();
    }
}

__global__ void k_fin(float* __restrict__ out, long long osize) {
    if (threadIdx.x == 0) {
        float s = 0.f;
        for (int i = 0; i < NBLK; i++) s += g_partial[i];
        float m = s * (1.0f / 33554432.0f);
        out[osize - 2] = __fadd_rn(m, 0.25f * m);
        float hsum = 0.f;
        for (int j = 0; j < NE; j++) {
            float e = (float)g_hist[j] * (1.0f / 65536.0f);
            hsum += e * logf(e + 1e-10f);
        }
        out[osize - 1] = expf(-hsum);
    }
}

extern "C" void kernel_launch(void* const* d_in, const int* in_sizes, int n_in,
                              void* d_out, int out_size) {
    const float* z     = (const float*)d_in[0];
    const float* emb   = (const float*)d_in[1];
    const float* stdp  = (const float*)d_in[2];
    const float* means = (const float*)d_in[3];
    const float* convw = (const float*)d_in[4];
    const float* convb = (const float*)d_in[5];
    float* out = (float*)d_out;

    cudaFuncSetAttribute(k_main, cudaFuncAttributeMaxDynamicSharedMemorySize, SMEM_TOTAL);
    k_init<<<1, 256>>>();
    k_prep_w<<<256, 512>>>(emb, stdp, means);
    k_prep_pw<<<256, 256>>>(convw, convb);
    k_main<<<NBLK, 256, SMEM_TOTAL>>>(z, out);
    k_fin<<<1, 32>>>(out, (long long)out_size);
}

// round 9
// speedup vs baseline: 1.2120x; 1.2120x over previous
#include <cuda_runtime.h>
#include <cstdint>
#include <math.h>

typedef unsigned int uint;

#define C_DIM 512
#define NE    256
#define HW    4096
#define NBLK  512
#define NSTG  32
#define THR   1e-3f

__device__ __align__(16) float g_whiP[NE * C_DIM];  // fragment-permuted tf32 hi
__device__ __align__(16) float g_wT [C_DIM * NE];   // fp32 codebook [c][j]
__device__ __align__(16) float g_pw [C_DIM * NE];   // projected codebook [o][j]
__device__ float g_n[NE];
__device__ int   g_hist[NE];
__device__ float g_partial[NBLK];

// stage: A[2][256][48B] | B[2][128][40B]
#define APL   12288
#define OFF_B 24576
#define BPL   5120
#define STAGE 34816
#define OFF_AP   69632
#define OFF_AT   70656
#define OFF_NRM  71168
#define OFF_IDX  72192
#define OFF_CD   72704
#define OFF_CI   74752
#define OFF_C2   76800
#define OFF_D1   78848
#define OFF_DS   79360
#define OFF_FC   79424
#define OFF_RD   79488
#define OFF_RI   79552
#define OFF_FL   79616
#define OFF_ZC   80128
#define OFF_HIST 82176
#define SMEM_TOTAL 83200

__device__ __forceinline__ uint s2u(const void* p) {
    uint a;
    asm("{ .reg .u64 t; cvta.to.shared.u64 t, %1; cvt.u32.u64 %0, t; }" : "=r"(a) : "l"(p));
    return a;
}
__device__ __forceinline__ float tf32r(float x) {
    uint r; asm("cvt.rna.tf32.f32 %0, %1;" : "=r"(r) : "f"(x));
    return __uint_as_float(r);
}
__device__ __forceinline__ void mma8(float* c, uint a0, uint a1, uint a2, uint a3,
                                     uint b0, uint b1) {
    asm volatile("mma.sync.aligned.m16n8k8.row.col.f32.tf32.tf32.f32 "
                 "{%0,%1,%2,%3}, {%4,%5,%6,%7}, {%8,%9}, {%0,%1,%2,%3};"
                 : "+f"(c[0]), "+f"(c[1]), "+f"(c[2]), "+f"(c[3])
                 : "r"(a0), "r"(a1), "r"(a2), "r"(a3), "r"(b0), "r"(b1));
}
#define CP16(dst, src) \
    asm volatile("cp.async.cg.shared.global [%0], [%1], 16;" :: "r"(dst), "l"(src))
#define CPCOMMIT() asm volatile("cp.async.commit_group;")
#define CPWAIT0()  asm volatile("cp.async.wait_group 0;")

__global__ void k_init() { g_hist[threadIdx.x] = 0; }

// grid 256 (code j), block 512 (channel c)
__global__ void k_prep_w(const float* __restrict__ emb,
                         const float* __restrict__ stdp,
                         const float* __restrict__ means) {
    __shared__ float wsum[16];
    int j = blockIdx.x, c = threadIdx.x;
    float s = fabsf(stdp[0]);
    float m = __fdiv_rn(means[0] + means[1] + means[2], 3.0f);
    float e = emb[(size_t)j * C_DIM + c];
    float v = __fadd_rn(__fmul_rn(e, s), m);
    g_wT[c * NE + j] = v;
    int chunk = c >> 4, p = (c >> 3) & 1, kin = c & 7;
    int pos = (kin & 3) * 2 + (kin >> 2);
    g_whiP[chunk * 4096 + p * 2048 + j * 8 + pos] = tf32r(v);
    float sq = v * v;
#pragma unroll
    for (int o = 16; o > 0; o >>= 1) sq += __shfl_xor_sync(0xffffffffu, sq, o);
    if ((c & 31) == 0) wsum[c >> 5] = sq;
    __syncthreads();
    if (c == 0) {
        float a = 0.f;
#pragma unroll
        for (int i = 0; i < 16; i++) a += wsum[i];
        g_n[j] = a;
    }
}

// grid 256 (2 channels each), block 256 (code j)
__global__ void k_prep_pw(const float* __restrict__ convw,
                          const float* __restrict__ convb) {
    __shared__ float cw[2][512];
    int bo = blockIdx.x * 2, j = threadIdx.x;
#pragma unroll
    for (int p = 0; p < 4; p++) {
        int i = j + 256 * p;
        cw[i >> 9][i & 511] = convw[(size_t)bo * 512 + i];
    }
    __syncthreads();
    float a0 = 0.f, a1 = 0.f;
#pragma unroll 8
    for (int c = 0; c < C_DIM; c++) {
        float wv = g_wT[c * NE + j];
        a0 = fmaf(cw[0][c], wv, a0);
        a1 = fmaf(cw[1][c], wv, a1);
    }
    g_pw[(size_t)bo * NE + j]       = __fadd_rn(a0, convb[bo]);
    g_pw[(size_t)(bo + 1) * NE + j] = __fadd_rn(a1, convb[bo + 1]);
}

__global__ __launch_bounds__(512, 1) void k_main(const float* __restrict__ z,
                                                 float* __restrict__ out) {
    extern __shared__ __align__(1024) char sm[];
    const uint sb = s2u(sm);
    const int tid = threadIdx.x;
    const int lane = tid & 31, warp = tid >> 5;
    const int g = lane >> 2, tig = lane & 3;
    const int wm = warp >> 2, wn = warp & 3;   // 4x4 warp grid: 64 codes x 32 tokens
    const int tok = tid & 127, h = (tid >> 7) & 1;
    const bool low = tid < 256;
    const int b = blockIdx.x >> 5;
    const int hw0 = (blockIdx.x & 31) << 7;
    const float* zb = z + (size_t)b * C_DIM * HW + hw0;

    if (tid < 256) {
        ((int*)(sm + OFF_HIST))[tid] = 0;
        ((float*)(sm + OFF_NRM))[tid] = g_n[tid];
    }
    if (tid == 0) *(int*)(sm + OFF_FC) = 0;

    float acc[4][4][4];
#pragma unroll
    for (int mt = 0; mt < 4; mt++)
#pragma unroll
        for (int nt = 0; nt < 4; nt++)
#pragma unroll
            for (int q = 0; q < 4; q++) acc[mt][nt][q] = 0.f;
    float regA = 0.f;
    float zr[8];

#define LDZ(s) do { \
    _Pragma("unroll") \
    for (int i = 0; i < 8; i++) zr[i] = zb[(size_t)((s) * 16 + h * 8 + i) * HW + tok]; \
    _Pragma("unroll") \
    for (int i = 0; i < 8; i++) regA = fmaf(zr[i], zr[i], regA); } while (0)

#define STZ(buf) do { \
    char* B_ = sm + (buf) * STAGE + OFF_B + h * BPL + tok * 40; \
    _Pragma("unroll") \
    for (int p = 0; p < 4; p++) \
        *(float2*)(B_ + p * 8) = make_float2(tf32r(zr[p]), tf32r(zr[p + 4])); \
    } while (0)

#define CB(s, buf) do { \
    _Pragma("unroll") \
    for (int i = 0; i < 4; i++) { \
        int q = (tid - 256) + 256 * i; \
        int p_ = q >> 9, m_ = (q >> 1) & 255, hf = q & 1; \
        CP16(sb + (buf) * STAGE + p_ * APL + m_ * 48 + hf * 16, \
             (const char*)g_whiP + (size_t)(s) * 16384 + q * 16); \
    } \
    CPCOMMIT(); } while (0)

#define COMPUTE(buf) do { \
    _Pragma("unroll") \
    for (int p = 0; p < 2; p++) { \
        const char* Ah = sm + (buf) * STAGE + p * APL + (wm * 64 + g) * 48 + tig * 8; \
        const char* Bh = sm + (buf) * STAGE + OFF_B + p * BPL + (wn * 32 + g) * 40 + tig * 8; \
        uint2 BHf[4]; \
        _Pragma("unroll") \
        for (int nt = 0; nt < 4; nt++) BHf[nt] = *(const uint2*)(Bh + nt * 320); \
        _Pragma("unroll") \
        for (int mt = 0; mt < 4; mt++) { \
            uint2 h0 = *(const uint2*)(Ah + mt * 768); \
            uint2 h1 = *(const uint2*)(Ah + mt * 768 + 384); \
            _Pragma("unroll") \
            for (int nt = 0; nt < 4; nt++) \
                mma8(acc[mt][nt], h0.x, h1.x, h0.y, h1.y, BHf[nt].x, BHf[nt].y); \
        } \
    } } while (0)

    // prologue
    if (!low) CB(0, 0);
    if (low) { LDZ(0); STZ(0); LDZ(1); }
    CPWAIT0();
    __syncthreads();

    for (int s = 0; s < NSTG; s++) {
        const int buf = s & 1;
        if (s < NSTG - 1) {
            if (low) {
                STZ(buf ^ 1);
                if (s < NSTG - 2) LDZ(s + 2);
            } else {
                CB(s + 1, buf ^ 1);
            }
        }
        COMPUTE(buf);
        CPWAIT0();
        __syncthreads();
    }

    // ---- epilogue: argmin with second-best tracking ----
    if (low) ((float*)(sm + OFF_AP))[h * 128 + tok] = regA;
    __syncthreads();
    if (tid < 128)
        ((float*)(sm + OFF_AT))[tid] =
            ((float*)(sm + OFF_AP))[tid] + ((float*)(sm + OFF_AP))[128 + tid];
    __syncthreads();

    const float* s_n = (const float*)(sm + OFF_NRM);
    const float* s_at = (const float*)(sm + OFF_AT);
#pragma unroll
    for (int nt = 0; nt < 4; nt++)
#pragma unroll
        for (int par = 0; par < 2; par++) {
            int t = wn * 32 + nt * 8 + 2 * tig + par;
            float At = s_at[t];
            float bd = __int_as_float(0x7f800000);
            float bd2 = bd;
            int bi = 0;
#pragma unroll
            for (int mt = 0; mt < 4; mt++) {
                int j0 = wm * 64 + mt * 16 + g;
                float d0 = __fadd_rn(__fadd_rn(At, s_n[j0]), -2.0f * acc[mt][nt][par]);
                float d1 = __fadd_rn(__fadd_rn(At, s_n[j0 + 8]), -2.0f * acc[mt][nt][2 + par]);
                if (d0 < bd) { bd2 = bd; bd = d0; bi = j0; } else if (d0 < bd2) bd2 = d0;
                if (d1 < bd) { bd2 = bd; bd = d1; bi = j0 + 8; } else if (d1 < bd2) bd2 = d1;
            }
#pragma unroll
            for (int o = 16; o >= 4; o >>= 1) {
                float od  = __shfl_xor_sync(0xffffffffu, bd, o);
                int   oi  = __shfl_xor_sync(0xffffffffu, bi, o);
                float od2 = __shfl_xor_sync(0xffffffffu, bd2, o);
                float nd2 = fminf(fmaxf(bd, od), fminf(bd2, od2));
                if (od < bd || (od == bd && oi < bi)) { bd = od; bi = oi; }
                bd2 = nd2;
            }
            if (g == 0) {
                ((float*)(sm + OFF_CD))[wm * 128 + t] = bd;
                ((int*)(sm + OFF_CI))[wm * 128 + t] = bi;
                ((float*)(sm + OFF_C2))[wm * 128 + t] = bd2;
            }
        }
    __syncthreads();

    float* P0 = (float*)sm;
    float* P1 = (float*)(sm + 32768);
    if (tid < 128) {
        float bd = ((float*)(sm + OFF_CD))[tid];
        int bi = ((int*)(sm + OFF_CI))[tid];
        float bd2 = ((float*)(sm + OFF_C2))[tid];
#pragma unroll
        for (int w = 1; w < 4; w++) {
            float d  = ((float*)(sm + OFF_CD))[w * 128 + tid];
            int   i2 = ((int*)(sm + OFF_CI))[w * 128 + tid];
            float e2 = ((float*)(sm + OFF_C2))[w * 128 + tid];
            float nd2 = fminf(fmaxf(bd, d), fminf(bd2, e2));
            if (d < bd || (d == bd && i2 < bi)) { bd = d; bi = i2; }
            bd2 = nd2;
        }
        ((int*)(sm + OFF_IDX))[tid] = bi;
        ((float*)(sm + OFF_D1))[tid] = bd;
        if (bd2 - bd < THR) {
            int p = atomicAdd((int*)(sm + OFF_FC), 1);
            ((int*)(sm + OFF_FL))[p] = tid;
        }
    } else if (tid >= 256) {
        int id = tid - 256;
#pragma unroll
        for (int p = 0; p < 8; p++)
            ((float4*)P0)[id + 256 * p] = ((const float4*)g_pw)[id + 256 * p];
    }
    __syncthreads();

    // ---- exact fp32 recheck for near-tie tokens ----
    const int cnt = *(const int*)(sm + OFF_FC);
    float* zcol = (float*)(sm + OFF_ZC);
    for (int q = 0; q < cnt; q++) {
        const int tk = ((const int*)(sm + OFF_FL))[q];
        zcol[tid] = zb[(size_t)tid * HW + tk];
        __syncthreads();
        if (tid < 256) {
            float d0 = 0.f, d1 = 0.f, d2 = 0.f, d3 = 0.f;
#pragma unroll 4
            for (int c = 0; c < C_DIM; c += 4) {
                d0 = fmaf(zcol[c],     g_wT[c * NE + tid],       d0);
                d1 = fmaf(zcol[c + 1], g_wT[(c + 1) * NE + tid], d1);
                d2 = fmaf(zcol[c + 2], g_wT[(c + 2) * NE + tid], d2);
                d3 = fmaf(zcol[c + 3], g_wT[(c + 3) * NE + tid], d3);
            }
            float dot = (d0 + d1) + (d2 + d3);
            float bd = __fadd_rn(__fadd_rn(s_at[tk], s_n[tid]), -2.0f * dot);
            int bi = tid;
#pragma unroll
            for (int o = 16; o > 0; o >>= 1) {
                float od = __shfl_xor_sync(0xffffffffu, bd, o);
                int   oi = __shfl_xor_sync(0xffffffffu, bi, o);
                if (od < bd || (od == bd && oi < bi)) { bd = od; bi = oi; }
            }
            if (lane == 0) {
                ((float*)(sm + OFF_RD))[warp] = bd;
                ((int*)(sm + OFF_RI))[warp] = bi;
            }
        }
        __syncthreads();
        if (tid == 0) {
            float fb = ((float*)(sm + OFF_RD))[0];
            int fi = ((int*)(sm + OFF_RI))[0];
#pragma unroll
            for (int w = 1; w < 8; w++) {
                float d = ((float*)(sm + OFF_RD))[w];
                int i2 = ((int*)(sm + OFF_RI))[w];
                if (d < fb || (d == fb && i2 < fi)) { fb = d; fi = i2; }
            }
            ((int*)(sm + OFF_IDX))[tk] = fi;
            ((float*)(sm + OFF_D1))[tk] = fb;
        }
        __syncthreads();
    }

    // ---- histogram + loss ----
    if (tid < 128) {
        atomicAdd(&((int*)(sm + OFF_HIST))[((const int*)(sm + OFF_IDX))[tid]], 1);
        float v = ((const float*)(sm + OFF_D1))[tid];
#pragma unroll
        for (int o = 16; o > 0; o >>= 1) v += __shfl_xor_sync(0xffffffffu, v, o);
        if (lane == 0) ((float*)(sm + OFF_DS))[warp] = v;
    }
    __syncthreads();
    if (tid == 0) {
        float* ds = (float*)(sm + OFF_DS);
        g_partial[blockIdx.x] = ds[0] + ds[1] + ds[2] + ds[3];
    }
    if (tid < 256) atomicAdd(&g_hist[tid], ((int*)(sm + OFF_HIST))[tid]);

    // ---- output gather (double-buffered pw chunks) ----
    const int mi = (tid < 128) ? ((const int*)(sm + OFF_IDX))[tid] : 0;
    const size_t outbase = (size_t)b * C_DIM * HW + hw0;
    for (int ch = 0; ch < 16; ch++) {
        float* cur = (ch & 1) ? P1 : P0;
        float* nxt = (ch & 1) ? P0 : P1;
        if (tid < 128) {
#pragma unroll 8
            for (int r = 0; r < 32; r++)
                out[outbase + (size_t)(ch * 32 + r) * HW + tid] = cur[r * NE + mi];
        } else if (tid >= 256 && ch < 15) {
            int id = tid - 256;
#pragma unroll
            for (int p = 0; p < 8; p++)
                ((float4*)nxt)[id + 256 * p] =
                    ((const float4*)g_pw)[(ch + 1) * 2048 + id + 256 * p];
        }
        __syncthreads();
    }
}

__global__ void k_fin(float* __restrict__ out, long long osize) {
    if (threadIdx.x == 0) {
        float s = 0.f;
        for (int i = 0; i < NBLK; i++) s += g_partial[i];
        float m = s * (1.0f / 33554432.0f);
        out[osize - 2] = __fadd_rn(m, 0.25f * m);
        float hsum = 0.f;
        for (int j = 0; j < NE; j++) {
            float e = (float)g_hist[j] * (1.0f / 65536.0f);
            hsum += e * logf(e + 1e-10f);
        }
        out[osize - 1] = expf(-hsum);
    }
}

extern "C" void kernel_launch(void* const* d_in, const int* in_sizes, int n_in,
                              void* d_out, int out_size) {
    const float* z     = (const float*)d_in[0];
    const float* emb   = (const float*)d_in[1];
    const float* stdp  = (const float*)d_in[2];
    const float* means = (const float*)d_in[3];
    const float* convw = (const float*)d_in[4];
    const float* convb = (const float*)d_in[5];
    float* out = (float*)d_out;

    cudaFuncSetAttribute(k_main, cudaFuncAttributeMaxDynamicSharedMemorySize, SMEM_TOTAL);
    k_init<<<1, 256>>>();
    k_prep_w<<<256, 512>>>(emb, stdp, means);
    k_prep_pw<<<256, 256>>>(convw, convb);
    k_main<<<NBLK, 512, SMEM_TOTAL>>>(z, out);
    k_fin<<<1, 32>>>(out, (long long)out_size);
}

// round 11
// speedup vs baseline: 2.0296x; 1.6746x over previous
#include <cuda_runtime.h>
#include <cstdint>
#include <math.h>

typedef unsigned int uint;

#define C_DIM 512
#define NE    256
#define HW    4096
#define NBLK  512
#define NSTG  32
#define THR   1e-3f

__device__ __align__(16) float g_whiP[NE * C_DIM];  // [stage][code][16B granules]
__device__ __align__(16) float g_wT [C_DIM * NE];   // fp32 codebook [c][j]
__device__ __align__(16) float g_pw [C_DIM * NE];   // projected codebook [o][j]
__device__ float g_n[NE];
__device__ int   g_hist[NE];
__device__ float g_partial[NBLK];

// stage: A[256 codes][64B swizzled] | B[128 toks][64B swizzled]
#define OFF_B    16384
#define STAGE    24576
#define OFF_AP   65536
#define OFF_AT   67584
#define OFF_NRM  68096
#define OFF_IDX  69120
#define OFF_CD   69632
#define OFF_CI   71680
#define OFF_C2   73728
#define OFF_D1   75776
#define OFF_DS   76288
#define OFF_FC   76304
#define OFF_RD   76320
#define OFF_RI   76384
#define OFF_FL   76448
#define OFF_ZC   76960
#define OFF_HIST 79008
#define SMEM_TOTAL 80128

__device__ __forceinline__ uint s2u(const void* p) {
    uint a;
    asm("{ .reg .u64 t; cvta.to.shared.u64 t, %1; cvt.u32.u64 %0, t; }" : "=r"(a) : "l"(p));
    return a;
}
__device__ __forceinline__ float tf32r(float x) {
    uint r; asm("cvt.rna.tf32.f32 %0, %1;" : "=r"(r) : "f"(x));
    return __uint_as_float(r);
}
// swizzled byte offset for row (code/token) r, 16B-group kr
__device__ __forceinline__ uint swz(int r, int kr) {
    return (uint)(r * 64 + kr * 16) ^ (uint)((r & 7) << 4);
}
__device__ __forceinline__ void mma8(float* c, uint a0, uint a1, uint a2, uint a3,
                                     uint b0, uint b1) {
    asm volatile("mma.sync.aligned.m16n8k8.row.col.f32.tf32.tf32.f32 "
                 "{%0,%1,%2,%3}, {%4,%5,%6,%7}, {%8,%9}, {%0,%1,%2,%3};"
                 : "+f"(c[0]), "+f"(c[1]), "+f"(c[2]), "+f"(c[3])
                 : "r"(a0), "r"(a1), "r"(a2), "r"(a3), "r"(b0), "r"(b1));
}
#define LDSM4(r, addr) \
    asm volatile("ldmatrix.sync.aligned.m8n8.x4.shared.b16 {%0,%1,%2,%3}, [%4];" \
                 : "=r"((r)[0]), "=r"((r)[1]), "=r"((r)[2]), "=r"((r)[3]) : "r"(addr))
#define CP16(dst, src) \
    asm volatile("cp.async.cg.shared.global [%0], [%1], 16;" :: "r"(dst), "l"(src))
#define CPCOMMIT() asm volatile("cp.async.commit_group;")
#define CPWAIT0()  asm volatile("cp.async.wait_group 0;")

// grid 256 (code j), block 512 (channel c); also zeroes g_hist
__global__ void k_prep_w(const float* __restrict__ emb,
                         const float* __restrict__ stdp,
                         const float* __restrict__ means) {
    __shared__ float wsum[16];
    int j = blockIdx.x, c = threadIdx.x;
    float s = fabsf(stdp[0]);
    float m = __fdiv_rn(means[0] + means[1] + means[2], 3.0f);
    float e = emb[(size_t)j * C_DIM + c];
    float v = __fadd_rn(__fmul_rn(e, s), m);
    g_wT[c * NE + j] = v;
    // permuted: [stage = c>>4][code j][c & 15]
    g_whiP[(c >> 4) * 4096 + j * 16 + (c & 15)] = tf32r(v);
    if (c == 0) g_hist[j] = 0;
    float sq = v * v;
#pragma unroll
    for (int o = 16; o > 0; o >>= 1) sq += __shfl_xor_sync(0xffffffffu, sq, o);
    if ((c & 31) == 0) wsum[c >> 5] = sq;
    __syncthreads();
    if (c == 0) {
        float a = 0.f;
#pragma unroll
        for (int i = 0; i < 16; i++) a += wsum[i];
        g_n[j] = a;
    }
}

// grid 256 (2 channels each), block 256 (code j)
__global__ void k_prep_pw(const float* __restrict__ convw,
                          const float* __restrict__ convb) {
    __shared__ float cw[2][512];
    int bo = blockIdx.x * 2, j = threadIdx.x;
#pragma unroll
    for (int p = 0; p < 4; p++) {
        int i = j + 256 * p;
        cw[i >> 9][i & 511] = convw[(size_t)bo * 512 + i];
    }
    __syncthreads();
    float a0 = 0.f, a1 = 0.f;
#pragma unroll 8
    for (int c = 0; c < C_DIM; c++) {
        float wv = g_wT[c * NE + j];
        a0 = fmaf(cw[0][c], wv, a0);
        a1 = fmaf(cw[1][c], wv, a1);
    }
    g_pw[(size_t)bo * NE + j]       = __fadd_rn(a0, convb[bo]);
    g_pw[(size_t)(bo + 1) * NE + j] = __fadd_rn(a1, convb[bo + 1]);
}

__global__ __launch_bounds__(512, 1) void k_main(const float* __restrict__ z,
                                                 float* __restrict__ out) {
    extern __shared__ __align__(1024) char sm[];
    const uint sb = s2u(sm);
    const int tid = threadIdx.x;
    const int lane = tid & 31, warp = tid >> 5;
    const int g = lane >> 2, tig = lane & 3;
    const int wm = warp >> 2, wn = warp & 3;   // 4x4 warps: 64 codes x 32 tokens
    const int tok = tid & 127, h = tid >> 7;   // h in 0..3: 4 channels per thread
    const int b = blockIdx.x >> 5;
    const int hw0 = (blockIdx.x & 31) << 7;
    const float* zb = z + (size_t)b * C_DIM * HW + hw0;

    if (tid < 256) {
        ((int*)(sm + OFF_HIST))[tid] = 0;
        ((float*)(sm + OFF_NRM))[tid] = g_n[tid];
    }
    if (tid == 0) *(int*)(sm + OFF_FC) = 0;

    // ldmatrix lane addresses (A: 4 tiles = m16k8 frag; B: x4 = two n8k8 frags)
    const int tA = lane >> 3, rA = lane & 7;
    const uint addrA = sb + swz(wm * 64 + (tA & 1) * 8 + rA, tA >> 1);
    const uint addrB = sb + OFF_B + swz(wn * 32 + (lane >> 4) * 8 + rA, (lane >> 3) & 1);

    float acc[4][4][4];
#pragma unroll
    for (int mt = 0; mt < 4; mt++)
#pragma unroll
        for (int nt = 0; nt < 4; nt++)
#pragma unroll
            for (int q = 0; q < 4; q++) acc[mt][nt][q] = 0.f;
    float regA = 0.f;
    float zr[4];

#define LDZ(s) do { \
    _Pragma("unroll") \
    for (int i = 0; i < 4; i++) zr[i] = zb[(size_t)((s) * 16 + h * 4 + i) * HW + tok]; \
    _Pragma("unroll") \
    for (int i = 0; i < 4; i++) regA = fmaf(zr[i], zr[i], regA); } while (0)

#define STZ(buf) do { \
    *(float4*)(sm + (buf) * STAGE + OFF_B + swz(tok, h)) = \
        make_float4(tf32r(zr[0]), tf32r(zr[1]), tf32r(zr[2]), tf32r(zr[3])); } while (0)

#define CB(s, buf) do { \
    _Pragma("unroll") \
    for (int i = 0; i < 2; i++) { \
        int q = tid + 512 * i; \
        CP16(sb + (buf) * STAGE + swz(q >> 2, q & 3), \
             (const char*)g_whiP + (size_t)(s) * 16384 + q * 16); \
    } \
    CPCOMMIT(); } while (0)

// NOTE: second k-half advance is XOR 32 (post-swizzle equivalent of +32
// pre-swizzle, since pre-swizzle bit5 is 0 for kr in {0,1}). Arithmetic +32
// carries into bit6 when the swizzle XOR set bit5 -> wrong row (R10 bug).
#define COMPUTE(buf) do { \
    const uint ab = addrA + (buf) * STAGE, bb = addrB + (buf) * STAGE; \
    _Pragma("unroll") \
    for (int p = 0; p < 2; p++) { \
        const uint kx = (uint)(p * 32); \
        uint b0[4], b1[4]; \
        LDSM4(b0, bb ^ kx); \
        LDSM4(b1, (bb + 1024) ^ kx); \
        _Pragma("unroll") \
        for (int mt = 0; mt < 4; mt++) { \
            uint a[4]; \
            LDSM4(a, (ab + mt * 1024) ^ kx); \
            mma8(acc[mt][0], a[0], a[1], a[2], a[3], b0[0], b0[1]); \
            mma8(acc[mt][1], a[0], a[1], a[2], a[3], b0[2], b0[3]); \
            mma8(acc[mt][2], a[0], a[1], a[2], a[3], b1[0], b1[1]); \
            mma8(acc[mt][3], a[0], a[1], a[2], a[3], b1[2], b1[3]); \
        } \
    } } while (0)

    // prologue
    CB(0, 0);
    LDZ(0); STZ(0); LDZ(1);
    CPWAIT0();
    __syncthreads();

    for (int s = 0; s < NSTG; s++) {
        const int buf = s & 1;
        if (s < NSTG - 1) {
            STZ(buf ^ 1);
            CB(s + 1, buf ^ 1);
            if (s < NSTG - 2) LDZ(s + 2);
        }
        COMPUTE(buf);
        CPWAIT0();
        __syncthreads();
    }

    // ---- epilogue: argmin with second-best tracking ----
    ((float*)(sm + OFF_AP))[h * 128 + tok] = regA;
    __syncthreads();
    if (tid < 128) {
        const float* ap = (const float*)(sm + OFF_AP);
        ((float*)(sm + OFF_AT))[tid] =
            ((ap[tid] + ap[128 + tid]) + (ap[256 + tid] + ap[384 + tid]));
    }
    __syncthreads();

    const float* s_n = (const float*)(sm + OFF_NRM);
    const float* s_at = (const float*)(sm + OFF_AT);
#pragma unroll
    for (int nt = 0; nt < 4; nt++)
#pragma unroll
        for (int par = 0; par < 2; par++) {
            int t = wn * 32 + nt * 8 + 2 * tig + par;
            float At = s_at[t];
            float bd = __int_as_float(0x7f800000);
            float bd2 = bd;
            int bi = 0;
#pragma unroll
            for (int mt = 0; mt < 4; mt++) {
                int j0 = wm * 64 + mt * 16 + g;
                float d0 = __fadd_rn(__fadd_rn(At, s_n[j0]), -2.0f * acc[mt][nt][par]);
                float d1 = __fadd_rn(__fadd_rn(At, s_n[j0 + 8]), -2.0f * acc[mt][nt][2 + par]);
                if (d0 < bd) { bd2 = bd; bd = d0; bi = j0; } else if (d0 < bd2) bd2 = d0;
                if (d1 < bd) { bd2 = bd; bd = d1; bi = j0 + 8; } else if (d1 < bd2) bd2 = d1;
            }
#pragma unroll
            for (int o = 16; o >= 4; o >>= 1) {
                float od  = __shfl_xor_sync(0xffffffffu, bd, o);
                int   oi  = __shfl_xor_sync(0xffffffffu, bi, o);
                float od2 = __shfl_xor_sync(0xffffffffu, bd2, o);
                float nd2 = fminf(fmaxf(bd, od), fminf(bd2, od2));
                if (od < bd || (od == bd && oi < bi)) { bd = od; bi = oi; }
                bd2 = nd2;
            }
            if (g == 0) {
                ((float*)(sm + OFF_CD))[wm * 128 + t] = bd;
                ((int*)(sm + OFF_CI))[wm * 128 + t] = bi;
                ((float*)(sm + OFF_C2))[wm * 128 + t] = bd2;
            }
        }
    __syncthreads();

    float* P0 = (float*)sm;
    float* P1 = (float*)(sm + 32768);
    if (tid < 128) {
        float bd = ((float*)(sm + OFF_CD))[tid];
        int bi = ((int*)(sm + OFF_CI))[tid];
        float bd2 = ((float*)(sm + OFF_C2))[tid];
#pragma unroll
        for (int w = 1; w < 4; w++) {
            float d  = ((float*)(sm + OFF_CD))[w * 128 + tid];
            int   i2 = ((int*)(sm + OFF_CI))[w * 128 + tid];
            float e2 = ((float*)(sm + OFF_C2))[w * 128 + tid];
            float nd2 = fminf(fmaxf(bd, d), fminf(bd2, e2));
            if (d < bd || (d == bd && i2 < bi)) { bd = d; bi = i2; }
            bd2 = nd2;
        }
        ((int*)(sm + OFF_IDX))[tid] = bi;
        ((float*)(sm + OFF_D1))[tid] = bd;
        if (bd2 - bd < THR) {
            int p = atomicAdd((int*)(sm + OFF_FC), 1);
            ((int*)(sm + OFF_FL))[p] = tid;
        }
    } else if (tid >= 256) {
        int id = tid - 256;
#pragma unroll
        for (int p = 0; p < 8; p++)
            ((float4*)P0)[id + 256 * p] = ((const float4*)g_pw)[id + 256 * p];
    }
    __syncthreads();

    // ---- exact fp32 recheck for near-tie tokens ----
    const int cnt = *(const int*)(sm + OFF_FC);
    float* zcol = (float*)(sm + OFF_ZC);
    for (int q = 0; q < cnt; q++) {
        const int tk = ((const int*)(sm + OFF_FL))[q];
        zcol[tid] = zb[(size_t)tid * HW + tk];
        __syncthreads();
        if (tid < 256) {
            float d0 = 0.f, d1 = 0.f, d2 = 0.f, d3 = 0.f;
#pragma unroll 4
            for (int c = 0; c < C_DIM; c += 4) {
                d0 = fmaf(zcol[c],     g_wT[c * NE + tid],       d0);
                d1 = fmaf(zcol[c + 1], g_wT[(c + 1) * NE + tid], d1);
                d2 = fmaf(zcol[c + 2], g_wT[(c + 2) * NE + tid], d2);
                d3 = fmaf(zcol[c + 3], g_wT[(c + 3) * NE + tid], d3);
            }
            float dot = (d0 + d1) + (d2 + d3);
            float bd = __fadd_rn(__fadd_rn(s_at[tk], s_n[tid]), -2.0f * dot);
            int bi = tid;
#pragma unroll
            for (int o = 16; o > 0; o >>= 1) {
                float od = __shfl_xor_sync(0xffffffffu, bd, o);
                int   oi = __shfl_xor_sync(0xffffffffu, bi, o);
                if (od < bd || (od == bd && oi < bi)) { bd = od; bi = oi; }
            }
            if (lane == 0) {
                ((float*)(sm + OFF_RD))[warp] = bd;
                ((int*)(sm + OFF_RI))[warp] = bi;
            }
        }
        __syncthreads();
        if (tid == 0) {
            float fb = ((float*)(sm + OFF_RD))[0];
            int fi = ((int*)(sm + OFF_RI))[0];
#pragma unroll
            for (int w = 1; w < 8; w++) {
                float d = ((float*)(sm + OFF_RD))[w];
                int i2 = ((int*)(sm + OFF_RI))[w];
                if (d < fb || (d == fb && i2 < fi)) { fb = d; fi = i2; }
            }
            ((int*)(sm + OFF_IDX))[tk] = fi;
            ((float*)(sm + OFF_D1))[tk] = fb;
        }
        __syncthreads();
    }

    // ---- histogram + loss ----
    if (tid < 128) {
        atomicAdd(&((int*)(sm + OFF_HIST))[((const int*)(sm + OFF_IDX))[tid]], 1);
        float v = ((const float*)(sm + OFF_D1))[tid];
#pragma unroll
        for (int o = 16; o > 0; o >>= 1) v += __shfl_xor_sync(0xffffffffu, v, o);
        if (lane == 0) ((float*)(sm + OFF_DS))[warp] = v;
    }
    __syncthreads();
    if (tid == 0) {
        float* ds = (float*)(sm + OFF_DS);
        g_partial[blockIdx.x] = ds[0] + ds[1] + ds[2] + ds[3];
    }
    if (tid < 256) atomicAdd(&g_hist[tid], ((int*)(sm + OFF_HIST))[tid]);

    // ---- output gather (double-buffered pw chunks) ----
    const int mi = (tid < 128) ? ((const int*)(sm + OFF_IDX))[tid] : 0;
    const size_t outbase = (size_t)b * C_DIM * HW + hw0;
    for (int ch = 0; ch < 16; ch++) {
        float* cur = (ch & 1) ? P1 : P0;
        float* nxt = (ch & 1) ? P0 : P1;
        if (tid < 128) {
#pragma unroll 8
            for (int r = 0; r < 32; r++)
                out[outbase + (size_t)(ch * 32 + r) * HW + tid] = cur[r * NE + mi];
        } else if (tid >= 256 && ch < 15) {
            int id = tid - 256;
#pragma unroll
            for (int p = 0; p < 8; p++)
                ((float4*)nxt)[id + 256 * p] =
                    ((const float4*)g_pw)[(ch + 1) * 2048 + id + 256 * p];
        }
        __syncthreads();
    }
}

__global__ void k_fin(float* __restrict__ out, long long osize) {
    __shared__ float red[8], red2[8];
    int t = threadIdx.x, lane = t & 31, w = t >> 5;   // 256 threads
    float s = g_partial[t] + g_partial[t + 256];
#pragma unroll
    for (int o = 16; o > 0; o >>= 1) s += __shfl_xor_sync(0xffffffffu, s, o);
    if (lane == 0) red[w] = s;
    float e = (float)g_hist[t] * (1.0f / 65536.0f);
    float hh = e * logf(e + 1e-10f);
#pragma unroll
    for (int o = 16; o > 0; o >>= 1) hh += __shfl_xor_sync(0xffffffffu, hh, o);
    if (lane == 0) red2[w] = hh;
    __syncthreads();
    if (t == 0) {
        float ts = 0.f, th = 0.f;
#pragma unroll
        for (int i = 0; i < 8; i++) { ts += red[i]; th += red2[i]; }
        float m = ts * (1.0f / 33554432.0f);
        out[osize - 2] = __fadd_rn(m, 0.25f * m);
        out[osize - 1] = expf(-th);
    }
}

extern "C" void kernel_launch(void* const* d_in, const int* in_sizes, int n_in,
                              void* d_out, int out_size) {
    const float* z     = (const float*)d_in[0];
    const float* emb   = (const float*)d_in[1];
    const float* stdp  = (const float*)d_in[2];
    const float* means = (const float*)d_in[3];
    const float* convw = (const float*)d_in[4];
    const float* convb = (const float*)d_in[5];
    float* out = (float*)d_out;

    cudaFuncSetAttribute(k_main, cudaFuncAttributeMaxDynamicSharedMemorySize, SMEM_TOTAL);
    k_prep_w<<<256, 512>>>(emb, stdp, means);
    k_prep_pw<<<256, 256>>>(convw, convb);
    k_main<<<NBLK, 512, SMEM_TOTAL>>>(z, out);
    k_fin<<<1, 256>>>(out, (long long)out_size);
}